// round 4
// baseline (speedup 1.0000x reference)
#include <cuda_runtime.h>
#include <math.h>

#define BB 256
#define SS 128
#define DIN 64
#define DOUT 64
#define HH 1024
#define H4 4096
#define NHEAD 4
#define HDIM 256
#define NSTEPS 16

// ---------------- scratch (static device allocations; no cudaMalloc) ----------------
__device__ float g_xT[SS * BB * DIN];            // [s][b][k]   8 MB
__device__ float g_pre[SS * BB * H4];            // 512 MB (reused: pre0 then pre1)
__device__ float g_y0[SS * BB * HH];             // enc layer0 outputs [t][b][h], 128 MB
__device__ float g_y1[SS * BB * HH];             // enc layer1 outputs, 128 MB
__device__ float g_Kp[SS * BB * HH];             // 128 MB
__device__ float g_Vp[SS * BB * HH];             // 128 MB
__device__ float g_z[BB * H4];                   // gate pre-activations scratch, 4 MB
__device__ float g_c0[BB * HH];
__device__ float g_c1[BB * HH];
__device__ float g_zeros[BB * HH];
__device__ float g_dh0[2][BB * HH];
__device__ float g_dh1[2][BB * HH];
__device__ float g_q[BB * HH];
__device__ float g_ctx[BB * HH];
__device__ float g_att[BB * HH];
__device__ float g_comb[BB * HH];

// ---------------- small kernels ----------------
__device__ __forceinline__ float sigf(float x) { return 1.0f / (1.0f + expf(-x)); }

__global__ void k_zero3(float* a, float* b, float* c) {
    int i = blockIdx.x * blockDim.x + threadIdx.x;
    if (i < BB * HH) { a[i] = 0.f; b[i] = 0.f; c[i] = 0.f; }
}

// x[b][s][k] -> xT[s][b][k]
__global__ void k_transpose_x(const float* __restrict__ x, float* __restrict__ xT) {
    int i = blockIdx.x * blockDim.x + threadIdx.x;
    if (i >= SS * BB * DIN) return;
    int k = i % DIN;
    int b = (i / DIN) % BB;
    int s = i / (DIN * BB);
    xT[i] = x[(b * SS + s) * DIN + k];
}

// z[b][4H] (+bias), c in/out, h out
__global__ void k_gates(const float* __restrict__ z, const float* __restrict__ bias,
                        float* __restrict__ c, float* __restrict__ h) {
    int idx = blockIdx.x * blockDim.x + threadIdx.x;
    if (idx >= BB * HH) return;
    int b = idx >> 10;
    int j = idx & (HH - 1);
    const float* zb = z + b * H4;
    float gi = sigf(zb[j] + bias[j]);
    float gf = sigf(zb[HH + j] + bias[HH + j]);
    float gg = tanhf(zb[2 * HH + j] + bias[2 * HH + j]);
    float go = sigf(zb[3 * HH + j] + bias[3 * HH + j]);
    float cn = gf * c[idx] + gi * gg;
    c[idx] = cn;
    h[idx] = go * tanhf(cn);
}

// one block per (b, head); 256 threads (= HDIM)
__global__ void k_attn(const float* __restrict__ q, const float* __restrict__ Kp,
                       const float* __restrict__ Vp, float* __restrict__ ctx) {
    int b = blockIdx.x / NHEAD;
    int n = blockIdx.x % NHEAD;
    int tid = threadIdx.x;
    int lane = tid & 31;
    int warp = tid >> 5;

    __shared__ float qs[HDIM];
    __shared__ float sc[SS];
    __shared__ float red[8];

    qs[tid] = q[b * HH + n * HDIM + tid];
    __syncthreads();

    // scores[s] = (q . K[s]) / 16
    for (int s = warp; s < SS; s += 8) {
        const float* kp = Kp + ((size_t)s * BB + b) * HH + n * HDIM;
        float p = 0.f;
        #pragma unroll
        for (int d = lane; d < HDIM; d += 32) p += qs[d] * kp[d];
        #pragma unroll
        for (int o = 16; o > 0; o >>= 1) p += __shfl_xor_sync(0xffffffffu, p, o);
        if (lane == 0) sc[s] = p * (1.0f / 16.0f);
    }
    __syncthreads();

    // softmax over s (128 valid entries)
    float v = (tid < SS) ? sc[tid] : -1e30f;
    float m = v;
    #pragma unroll
    for (int o = 16; o > 0; o >>= 1) m = fmaxf(m, __shfl_xor_sync(0xffffffffu, m, o));
    if (lane == 0) red[warp] = m;
    __syncthreads();
    if (tid == 0) {
        float mm = red[0];
        #pragma unroll
        for (int w = 1; w < 8; w++) mm = fmaxf(mm, red[w]);
        red[0] = mm;
    }
    __syncthreads();
    float mx = red[0];
    float e = (tid < SS) ? expf(sc[tid] - mx) : 0.f;
    float ssum = e;
    #pragma unroll
    for (int o = 16; o > 0; o >>= 1) ssum += __shfl_xor_sync(0xffffffffu, ssum, o);
    __syncthreads();  // everyone done reading red[0]
    if (lane == 0) red[warp] = ssum;
    __syncthreads();
    if (tid == 0) {
        float t2 = 0.f;
        #pragma unroll
        for (int w = 0; w < 8; w++) t2 += red[w];
        red[0] = t2;
    }
    __syncthreads();
    float inv = 1.0f / red[0];
    if (tid < SS) sc[tid] = e * inv;
    __syncthreads();

    // ctx[d] = sum_s w[s] * V[s][b][n*HD + d]
    float acc = 0.f;
    const float* vb = Vp + (size_t)b * HH + n * HDIM + tid;
    for (int s = 0; s < SS; s++) acc += sc[s] * vb[(size_t)s * BB * HH];
    ctx[b * HH + n * HDIM + tid] = acc;
}

// ---------------- generic fp32 tiled GEMM: C = A@B [+Cadd][+bias][relu] ----------------
template <int BM, int BN, int BK, int TM, int TN>
__global__ void __launch_bounds__((BM / TM) * (BN / TN))
gemm_f32(const float* __restrict__ A, int lda,
         const float* __restrict__ Bm, int ldb,
         float* __restrict__ C, int ldc,
         const float* __restrict__ Cadd,
         const float* __restrict__ bias,
         int K, int relu) {
    constexpr int THREADS = (BM / TM) * (BN / TN);
    __shared__ float As[BK][BM + 1];
    __shared__ float Bs[BK][BN + 1];
    int tid = threadIdx.x;
    int tx = tid % (BN / TN);
    int ty = tid / (BN / TN);
    int row0 = blockIdx.y * BM;
    int col0 = blockIdx.x * BN;

    float acc[TM][TN];
    #pragma unroll
    for (int i = 0; i < TM; i++)
        #pragma unroll
        for (int j = 0; j < TN; j++) acc[i][j] = 0.f;

    for (int k0 = 0; k0 < K; k0 += BK) {
        #pragma unroll
        for (int i = tid; i < BM * BK; i += THREADS) {
            int m = i / BK, k = i % BK;
            As[k][m] = A[(row0 + m) * lda + k0 + k];
        }
        #pragma unroll
        for (int i = tid; i < BK * BN; i += THREADS) {
            int k = i / BN, n = i % BN;
            Bs[k][n] = Bm[(k0 + k) * ldb + col0 + n];
        }
        __syncthreads();
        #pragma unroll
        for (int kk = 0; kk < BK; kk++) {
            float ra[TM], rb[TN];
            #pragma unroll
            for (int i = 0; i < TM; i++) ra[i] = As[kk][ty * TM + i];
            #pragma unroll
            for (int j = 0; j < TN; j++) rb[j] = Bs[kk][tx * TN + j];
            #pragma unroll
            for (int i = 0; i < TM; i++)
                #pragma unroll
                for (int j = 0; j < TN; j++) acc[i][j] += ra[i] * rb[j];
        }
        __syncthreads();
    }

    #pragma unroll
    for (int i = 0; i < TM; i++) {
        int r = row0 + ty * TM + i;
        #pragma unroll
        for (int j = 0; j < TN; j++) {
            int cc = col0 + tx * TN + j;
            float val = acc[i][j];
            if (Cadd) val += Cadd[r * ldc + cc];
            if (bias) val += bias[cc];
            if (relu) val = fmaxf(val, 0.f);
            C[r * ldc + cc] = val;
        }
    }
}

// host wrappers (M%BM==0, N%BN==0, K%16==0 guaranteed by call sites)
static void gemm128(const float* A, int lda, const float* B, int ldb,
                    float* C, int ldc, const float* Cadd, const float* bias,
                    int M, int N, int K, int relu) {
    dim3 g(N / 128, M / 128);
    gemm_f32<128, 128, 16, 8, 8><<<g, 256>>>(A, lda, B, ldb, C, ldc, Cadd, bias, K, relu);
}
static void gemm64(const float* A, int lda, const float* B, int ldb,
                   float* C, int ldc, const float* Cadd, const float* bias,
                   int M, int N, int K, int relu) {
    dim3 g(N / 64, M / 64);
    gemm_f32<64, 64, 16, 4, 4><<<g, 256>>>(A, lda, B, ldb, C, ldc, Cadd, bias, K, relu);
}

// ---------------- launch ----------------
extern "C" void kernel_launch(void* const* d_in, const int* in_sizes, int n_in,
                              void* d_out, int out_size) {
    if (n_in < 25) return;
    const float* x     = (const float*)d_in[0];
    const float* e0_Wx = (const float*)d_in[1];
    const float* e0_Wh = (const float*)d_in[2];
    const float* e0_b  = (const float*)d_in[3];
    const float* e1_Wx = (const float*)d_in[4];
    const float* e1_Wh = (const float*)d_in[5];
    const float* e1_b  = (const float*)d_in[6];
    const float* d0_Wx = (const float*)d_in[7];
    const float* d0_Wh = (const float*)d_in[8];
    const float* d0_b  = (const float*)d_in[9];
    const float* d1_Wx = (const float*)d_in[10];
    const float* d1_Wh = (const float*)d_in[11];
    const float* d1_b  = (const float*)d_in[12];

    // order-robust parse of the remaining tensors by element count
    const float* Wm[4] = {0, 0, 0, 0};   // Wq, Wk, Wv, Wo
    const float* vec[5] = {0, 0, 0, 0, 0};  // bq, bk, bv, bo, fc_b
    const float* fc_W = 0; const float* out_W = 0; const float* out_b = 0;
    int nm = 0, nv = 0;
    for (int i = 13; i < n_in; i++) {
        int sz = in_sizes[i];
        const float* p = (const float*)d_in[i];
        if (sz == HH * HH)           { if (nm < 4) Wm[nm++] = p; }
        else if (sz == HH)           { if (nv < 5) vec[nv++] = p; }
        else if (sz == 2 * HH * HH)  fc_W = p;
        else if (sz == HH * DOUT)    out_W = p;
        else if (sz == DOUT)         out_b = p;
    }
    const float *Wq = Wm[0], *Wk = Wm[1], *Wv = Wm[2], *Wo = Wm[3];
    const float *bq = vec[0], *bk = vec[1], *bv = vec[2], *bo = vec[3], *fc_b = vec[4];

    float *xT, *pre, *y0, *y1, *Kp, *Vp, *z, *c0, *c1, *zeros, *dh0b, *dh1b;
    float *q, *ctx, *att, *comb;
    cudaGetSymbolAddress((void**)&xT, g_xT);
    cudaGetSymbolAddress((void**)&pre, g_pre);
    cudaGetSymbolAddress((void**)&y0, g_y0);
    cudaGetSymbolAddress((void**)&y1, g_y1);
    cudaGetSymbolAddress((void**)&Kp, g_Kp);
    cudaGetSymbolAddress((void**)&Vp, g_Vp);
    cudaGetSymbolAddress((void**)&z, g_z);
    cudaGetSymbolAddress((void**)&c0, g_c0);
    cudaGetSymbolAddress((void**)&c1, g_c1);
    cudaGetSymbolAddress((void**)&zeros, g_zeros);
    cudaGetSymbolAddress((void**)&dh0b, g_dh0);
    cudaGetSymbolAddress((void**)&dh1b, g_dh1);
    cudaGetSymbolAddress((void**)&q, g_q);
    cudaGetSymbolAddress((void**)&ctx, g_ctx);
    cudaGetSymbolAddress((void**)&att, g_att);
    cudaGetSymbolAddress((void**)&comb, g_comb);
    float* dh0[2] = {dh0b, dh0b + BB * HH};
    float* dh1[2] = {dh1b, dh1b + BB * HH};
    float* outp = (float*)d_out;

    const int BH = BB * HH;

    // reset state (determinism across graph replays)
    k_zero3<<<(BH + 255) / 256, 256>>>(c0, c1, zeros);

    // ---- encoder layer 0 ----
    k_transpose_x<<<(SS * BB * DIN + 255) / 256, 256>>>(x, xT);
    gemm128(xT, DIN, e0_Wx, H4, pre, H4, nullptr, nullptr, SS * BB, H4, DIN, 0);
    for (int t = 0; t < SS; t++) {
        const float* hin = t ? (y0 + (size_t)(t - 1) * BH) : zeros;
        gemm64(hin, HH, e0_Wh, H4, z, H4, pre + (size_t)t * BB * H4, nullptr, BB, H4, HH, 0);
        k_gates<<<BH / 256, 256>>>(z, e0_b, c0, y0 + (size_t)t * BH);
    }

    // ---- encoder layer 1 ----
    gemm128(y0, HH, e1_Wx, H4, pre, H4, nullptr, nullptr, SS * BB, H4, HH, 0);
    for (int t = 0; t < SS; t++) {
        const float* hin = t ? (y1 + (size_t)(t - 1) * BH) : zeros;
        gemm64(hin, HH, e1_Wh, H4, z, H4, pre + (size_t)t * BB * H4, nullptr, BB, H4, HH, 0);
        k_gates<<<BH / 256, 256>>>(z, e1_b, c1, y1 + (size_t)t * BH);
    }

    // ---- K / V projections over all encoder outputs ----
    gemm128(y1, HH, Wk, HH, Kp, HH, nullptr, bk, SS * BB, HH, HH, 0);
    gemm128(y1, HH, Wv, HH, Vp, HH, nullptr, bv, SS * BB, HH, HH, 0);

    // ---- decoder ----
    for (int t = 0; t < NSTEPS; t++) {
        const float* xin  = t ? (outp + (t - 1) * DOUT) : zeros;
        int xlda          = t ? (NSTEPS * DOUT) : DOUT;
        const float* h0in = t ? dh0[(t - 1) & 1] : (y0 + (size_t)(SS - 1) * BH);
        const float* h1in = t ? dh1[(t - 1) & 1] : (y1 + (size_t)(SS - 1) * BH);
        float* h0o = dh0[t & 1];
        float* h1o = dh1[t & 1];

        // cell d0: z = xin@Wx + h0@Wh ; gates (c0 carries encoder-final state)
        gemm64(xin, xlda, d0_Wx, H4, z, H4, nullptr, nullptr, BB, H4, DOUT, 0);
        gemm64(h0in, HH, d0_Wh, H4, z, H4, z, nullptr, BB, H4, HH, 0);
        k_gates<<<BH / 256, 256>>>(z, d0_b, c0, h0o);

        // cell d1: z = h0o@Wx + h1@Wh
        gemm64(h0o, HH, d1_Wx, H4, z, H4, nullptr, nullptr, BB, H4, HH, 0);
        gemm64(h1in, HH, d1_Wh, H4, z, H4, z, nullptr, BB, H4, HH, 0);
        k_gates<<<BH / 256, 256>>>(z, d1_b, c1, h1o);

        // attention
        gemm64(h1o, HH, Wq, HH, q, HH, nullptr, bq, BB, HH, HH, 0);
        k_attn<<<BB * NHEAD, HDIM>>>(q, Kp, Vp, ctx);
        gemm64(ctx, HH, Wo, HH, att, HH, nullptr, bo, BB, HH, HH, 0);

        // comb = relu([h1o, att] @ fc_W + fc_b)
        gemm64(h1o, HH, fc_W, HH, comb, HH, nullptr, nullptr, BB, HH, HH, 0);
        gemm64(att, HH, fc_W + (size_t)HH * HH, HH, comb, HH, comb, fc_b, BB, HH, HH, 1);

        // out[:, t, :] = comb @ out_W + out_b
        gemm64(comb, HH, out_W, DOUT, outp + t * DOUT, NSTEPS * DOUT,
               nullptr, out_b, BB, DOUT, HH, 0);
    }
}